// round 5
// baseline (speedup 1.0000x reference)
#include <cuda_runtime.h>
#include <cuda_fp16.h>
#include <cstdint>
#include <cstddef>

#define Bz 128
#define Ez 512
#define Dz 512
#define Vz 275
#define Pz 576
#define Tz 300
#define TM1 299
#define EP (Ez*Pz)
#define GRID 128
#define NTHR 512

// ---------------- scratch (device globals; no allocs allowed) ----------------
__device__ __half g_Ws[(size_t)Bz*Pz*Dz];     // 75.5 MB fp16: flat@W_w + W_b
__device__ __half g_featsh[(size_t)Bz*EP];    // 75.5 MB fp16 copy of feats
__device__ float g_fcwT[Vz*Dz];               // transposed fc weights [V][D]
__device__ float g_embW[Vz*2048];             // emb @ wih[:, :512]^T  [V][4D]
__device__ float g_mean[Bz*Ez];
__device__ float g_h[2][Bz*Dz];
__device__ float g_c[2][Bz*Dz];
__device__ float g_p1[8][Bz*1024];            // per-step split-K partials (hU|gate)
__device__ float g_xin[Bz*Dz];                // gate*ctx only (emb via embW)
__device__ float g_part[2][Bz*2048];          // split-K partials for LSTM gemm

// ---------------- software grid barrier --------------------------------------
__device__ unsigned g_bar_count;
__device__ volatile unsigned g_bar_gen;

__device__ __forceinline__ void gridsync() {
    __syncthreads();
    if (threadIdx.x == 0) {
        __threadfence();
        unsigned gen = g_bar_gen;
        if (atomicAdd(&g_bar_count, 1u) == GRID - 1) {
            g_bar_count = 0;
            __threadfence();
            g_bar_gen = gen + 1;
        } else {
            while (g_bar_gen == gen) {}
        }
        __threadfence();
    }
    __syncthreads();
}

// ---------------- packed f32x2 helpers ---------------------------------------
__device__ __forceinline__ void ffma2(unsigned long long& d,
                                      unsigned long long a,
                                      unsigned long long b) {
    asm("fma.rn.f32x2 %0, %1, %2, %3;" : "=l"(d) : "l"(a), "l"(b), "l"(d));
}
__device__ __forceinline__ unsigned long long pack2dup(float x) {
    unsigned long long r; asm("mov.b64 %0, {%1, %1};" : "=l"(r) : "f"(x));
    return r;
}
__device__ __forceinline__ void unpack2(unsigned long long v, float& lo, float& hi) {
    asm("mov.b64 {%0, %1}, %2;" : "=f"(lo), "=f"(hi) : "l"(v));
}

// ---------------- activation helpers -----------------------------------------
__device__ __forceinline__ float tanh_mufu(float x) {
    float y; asm("tanh.approx.f32 %0, %1;" : "=f"(y) : "f"(x));
    return y;
}
__device__ __forceinline__ float fast_tanh(float x) {
    float t = fminf(fmaxf(x * 2.885390081777927f, -252.0f), 252.0f);
    float z; asm("ex2.approx.f32 %0, %1;" : "=f"(z) : "f"(t));
    float den = z + 1.0f;
    float r; asm("rcp.approx.f32 %0, %1;" : "=f"(r) : "f"(den));
    return (z - 1.0f) * r;
}
__device__ __forceinline__ float fast_sigmoid(float x) {
    float t = fminf(fmaxf(x * -1.4426950408889634f, -252.0f), 252.0f);
    float z; asm("ex2.approx.f32 %0, %1;" : "=f"(z) : "f"(t));
    float den = z + 1.0f;
    float r; asm("rcp.approx.f32 %0, %1;" : "=f"(r) : "f"(den));
    return r;
}
__device__ __forceinline__ void h8_to_f(const uint4& u, float* f) {
    float2 a = __half22float2(*reinterpret_cast<const __half2*>(&u.x));
    float2 b = __half22float2(*reinterpret_cast<const __half2*>(&u.y));
    float2 c = __half22float2(*reinterpret_cast<const __half2*>(&u.z));
    float2 d = __half22float2(*reinterpret_cast<const __half2*>(&u.w));
    f[0]=a.x; f[1]=a.y; f[2]=b.x; f[3]=b.y; f[4]=c.x; f[5]=c.y; f[6]=d.x; f[7]=d.y;
}

// ======= launch 1: mean + fcw transpose + dec_len ============================
__global__ void prep_misc_kernel(const float* __restrict__ feats,
                                 const float* __restrict__ fcw,
                                 const int* __restrict__ lengths,
                                 float* __restrict__ dec) {
    int bx = blockIdx.x, tid = threadIdx.x;
    if (bx < 8192) {
        int warp = tid >> 5, lane = tid & 31;
        int idx = bx * 8 + warp;
        int b = idx >> 9, e = idx & 511;
        const float* src = feats + (size_t)b * EP + (size_t)e * Pz;
        float acc = 0.f;
        #pragma unroll
        for (int k = 0; k < 18; k++) acc += src[lane + k * 32];
        #pragma unroll
        for (int o = 16; o; o >>= 1) acc += __shfl_down_sync(0xffffffffu, acc, o);
        if (lane == 0) g_mean[idx] = acc * (1.0f / 576.0f);
    } else if (bx < 8742) {
        int idx = (bx - 8192) * 256 + tid;
        int v = idx >> 9, d = idx & 511;
        g_fcwT[v * 512 + d] = fcw[d * Vz + v];
    } else {
        if (tid < Bz) dec[tid] = (float)(lengths[tid] - 1);
    }
}

// ======= launch 2: f2h + init h0/c0 gemm =====================================
__global__ void prep2_kernel(const float* __restrict__ feats,
                             const float* __restrict__ W1,
                             const float* __restrict__ W2,
                             const float* __restrict__ b1,
                             const float* __restrict__ b2) {
    int bx = blockIdx.x, tid = threadIdx.x;
    if (bx < 18432) {
        size_t i = ((size_t)bx * 256 + tid) * 8;
        float4 v0 = *reinterpret_cast<const float4*>(feats + i);
        float4 v1 = *reinterpret_cast<const float4*>(feats + i + 4);
        __half2 h0 = __floats2half2_rn(v0.x, v0.y);
        __half2 h1 = __floats2half2_rn(v0.z, v0.w);
        __half2 h2 = __floats2half2_rn(v1.x, v1.y);
        __half2 h3 = __floats2half2_rn(v1.z, v1.w);
        uint4 o;
        o.x = *reinterpret_cast<unsigned*>(&h0);
        o.y = *reinterpret_cast<unsigned*>(&h1);
        o.z = *reinterpret_cast<unsigned*>(&h2);
        o.w = *reinterpret_cast<unsigned*>(&h3);
        *reinterpret_cast<uint4*>(g_featsh + i) = o;
        return;
    }
    int jt = bx - 18432;
    const float* W = (jt < 8) ? W1 : W2;
    const float* bias = (jt < 8) ? b1 : b2;
    int wj0 = ((jt < 8) ? jt : jt - 8) * 64;
    __shared__ float As[8][128];
    __shared__ float Bs[8][64];
    int tx = tid & 15, ty = tid >> 4;
    float acc[8][4] = {};
    for (int kk = 0; kk < 512; kk += 8) {
        {
            int b = tid >> 1, r4 = (tid & 1) * 4;
            float4 v = *reinterpret_cast<const float4*>(&g_mean[b * 512 + kk + r4]);
            As[r4 + 0][b] = v.x; As[r4 + 1][b] = v.y; As[r4 + 2][b] = v.z; As[r4 + 3][b] = v.w;
        }
        if (tid < 128) {
            int j4 = (tid & 15) * 4, r = tid >> 4;
            float4 v = *reinterpret_cast<const float4*>(&W[(kk + r) * 512 + wj0 + j4]);
            Bs[r][j4 + 0] = v.x; Bs[r][j4 + 1] = v.y; Bs[r][j4 + 2] = v.z; Bs[r][j4 + 3] = v.w;
        }
        __syncthreads();
        #pragma unroll
        for (int r = 0; r < 8; r++) {
            float4 w4 = *reinterpret_cast<const float4*>(&Bs[r][tx * 4]);
            float4 a0 = *reinterpret_cast<const float4*>(&As[r][ty * 8]);
            float4 a1 = *reinterpret_cast<const float4*>(&As[r][ty * 8 + 4]);
            float a[8] = {a0.x, a0.y, a0.z, a0.w, a1.x, a1.y, a1.z, a1.w};
            float w[4] = {w4.x, w4.y, w4.z, w4.w};
            #pragma unroll
            for (int i = 0; i < 8; i++)
                #pragma unroll
                for (int jj = 0; jj < 4; jj++)
                    acc[i][jj] = fmaf(a[i], w[jj], acc[i][jj]);
        }
        __syncthreads();
    }
    float* dst = (jt < 8) ? g_h[0] : g_c[0];
    int j = wj0 + tx * 4;
    float4 bb = *reinterpret_cast<const float4*>(&bias[j]);
    #pragma unroll
    for (int i = 0; i < 8; i++) {
        int b = ty * 8 + i;
        float4 v = {acc[i][0] + bb.x, acc[i][1] + bb.y, acc[i][2] + bb.z, acc[i][3] + bb.w};
        *reinterpret_cast<float4*>(&dst[b * 512 + j]) = v;
    }
}

// ======= launch 3: embW[v][j] = sum_k emb[v][k] * wih[j][k]  (k<512) =========
__global__ void embw_kernel(const float* __restrict__ emb,
                            const float* __restrict__ wih) {
    __shared__ float er[4][512];
    int tid = threadIdx.x;
    int v0 = blockIdx.y * 4, j0 = blockIdx.x * 1024;
    for (int i = tid; i < 2048; i += 512) {
        int vv = v0 + (i >> 9);
        er[i >> 9][i & 511] = (vv < Vz) ? emb[vv * 512 + (i & 511)] : 0.f;
    }
    __syncthreads();
    #pragma unroll
    for (int jj = 0; jj < 2; jj++) {
        int j = j0 + jj * 512 + tid;
        const float* wr = wih + (size_t)j * 1024;
        float acc[4] = {};
        for (int k = 0; k < 512; k += 4) {
            float4 w = *reinterpret_cast<const float4*>(wr + k);
            #pragma unroll
            for (int r = 0; r < 4; r++) {
                float4 e4 = *reinterpret_cast<const float4*>(&er[r][k]);
                acc[r] = fmaf(w.x, e4.x, acc[r]);
                acc[r] = fmaf(w.y, e4.y, acc[r]);
                acc[r] = fmaf(w.z, e4.z, acc[r]);
                acc[r] = fmaf(w.w, e4.w, acc[r]);
            }
        }
        #pragma unroll
        for (int r = 0; r < 4; r++)
            if (v0 + r < Vz) g_embW[(v0 + r) * 2048 + j] = acc[r];
    }
}

// ======= launch 4: Ws precompute (fp16) ======================================
__global__ void ws_gemm_kernel(const float* __restrict__ feats,
                               const float* __restrict__ Ww,
                               const float* __restrict__ Wb) {
    int b = blockIdx.z;
    int p0 = blockIdx.x * 64;
    int d0 = blockIdx.y * 64;
    __shared__ float As[8][64];
    __shared__ float Bs[8][64];
    int tid = threadIdx.x, tx = tid & 15, ty = tid >> 4;
    float acc[4][4] = {};
    const float* fb = feats + (size_t)b * EP;
    for (int kk = 0; kk < 512; kk += 8) {
        if (tid < 128) {
            int p4 = (tid & 15) * 4, r = tid >> 4;
            float4 v = *reinterpret_cast<const float4*>(&fb[(size_t)(kk + r) * Pz + p0 + p4]);
            As[r][p4 + 0] = v.x; As[r][p4 + 1] = v.y; As[r][p4 + 2] = v.z; As[r][p4 + 3] = v.w;
        } else {
            int t2 = tid - 128;
            int d4 = (t2 & 15) * 4, r = t2 >> 4;
            float4 v = *reinterpret_cast<const float4*>(&Ww[(kk + r) * 512 + d0 + d4]);
            Bs[r][d4 + 0] = v.x; Bs[r][d4 + 1] = v.y; Bs[r][d4 + 2] = v.z; Bs[r][d4 + 3] = v.w;
        }
        __syncthreads();
        #pragma unroll
        for (int r = 0; r < 8; r++) {
            float4 a4 = *reinterpret_cast<const float4*>(&As[r][ty * 4]);
            float4 w4 = *reinterpret_cast<const float4*>(&Bs[r][tx * 4]);
            float a[4] = {a4.x, a4.y, a4.z, a4.w};
            float w[4] = {w4.x, w4.y, w4.z, w4.w};
            #pragma unroll
            for (int i = 0; i < 4; i++)
                #pragma unroll
                for (int jj = 0; jj < 4; jj++)
                    acc[i][jj] = fmaf(a[i], w[jj], acc[i][jj]);
        }
        __syncthreads();
    }
    float4 wb4 = *reinterpret_cast<const float4*>(&Wb[d0 + tx * 4]);
    #pragma unroll
    for (int i = 0; i < 4; i++) {
        size_t row = (size_t)(b * Pz + p0 + ty * 4 + i);
        __half2 h01 = __floats2half2_rn(acc[i][0] + wb4.x, acc[i][1] + wb4.y);
        __half2 h23 = __floats2half2_rn(acc[i][2] + wb4.z, acc[i][3] + wb4.w);
        uint2 u;
        u.x = *reinterpret_cast<unsigned*>(&h01);
        u.y = *reinterpret_cast<unsigned*>(&h23);
        *reinterpret_cast<uint2*>(&g_Ws[row * 512 + d0 + tx * 4]) = u;
    }
}

// ============================================================================
//  launch 5: persistent decode, 299 steps, 4 phases/step
// ============================================================================
__global__ void __launch_bounds__(NTHR, 1) decode_kernel(
    const float* __restrict__ Uw,  const float* __restrict__ Ub,
    const float* __restrict__ vw,  const float* __restrict__ vb,
    const float* __restrict__ fbw, const float* __restrict__ fbb,
    const int*   __restrict__ captions,
    const int*   __restrict__ lengths,
    const float* __restrict__ wih, const float* __restrict__ whh,
    const float* __restrict__ bih, const float* __restrict__ bhh,
    const float* __restrict__ fcb,
    float* __restrict__ preds_out, float* __restrict__ alphas_out)
{
    __shared__ __align__(16) float smem[6208];  // D: AsT 32*130 + Bs2 1024 ull
    const int bx = blockIdx.x, tid = threadIdx.x;
    const int wid = tid >> 5, lane = tid & 31;

    for (int t = 0; t < TM1; t++) {
        const int cur = t & 1;
        const float* h = g_h[cur];

        // ------------- Phase A: (hU | gate-raw) partials = h @ (U_w | f_beta_w)
        {
            int jt = bx & 15, kc = bx >> 4;
            const float* W = (jt < 8) ? Uw : fbw;
            int wj0 = ((jt < 8) ? jt : jt - 8) * 64;
            int k0 = kc * 64;
            float* As = smem;            // [8][128]
            float* Bs = smem + 1024;     // [8][64]
            int tx = tid & 15, ty = tid >> 4;
            float acc[4][4] = {};
            for (int kk = 0; kk < 64; kk += 8) {
                if (tid < 256) {
                    int b = tid >> 1, r4 = (tid & 1) * 4;
                    float4 v = *reinterpret_cast<const float4*>(&h[b * 512 + k0 + kk + r4]);
                    As[(r4 + 0) * 128 + b] = v.x; As[(r4 + 1) * 128 + b] = v.y;
                    As[(r4 + 2) * 128 + b] = v.z; As[(r4 + 3) * 128 + b] = v.w;
                } else if (tid < 384) {
                    int t2 = tid - 256;
                    int j4 = (t2 & 15) * 4, r = t2 >> 4;
                    float4 v = *reinterpret_cast<const float4*>(&W[(k0 + kk + r) * 512 + wj0 + j4]);
                    Bs[r * 64 + j4 + 0] = v.x; Bs[r * 64 + j4 + 1] = v.y;
                    Bs[r * 64 + j4 + 2] = v.z; Bs[r * 64 + j4 + 3] = v.w;
                }
                __syncthreads();
                #pragma unroll
                for (int r = 0; r < 8; r++) {
                    float4 w4 = *reinterpret_cast<const float4*>(&Bs[r * 64 + tx * 4]);
                    float4 a4 = *reinterpret_cast<const float4*>(&As[r * 128 + ty * 4]);
                    float a[4] = {a4.x, a4.y, a4.z, a4.w};
                    float w[4] = {w4.x, w4.y, w4.z, w4.w};
                    #pragma unroll
                    for (int i = 0; i < 4; i++)
                        #pragma unroll
                        for (int jj = 0; jj < 4; jj++)
                            acc[i][jj] = fmaf(a[i], w[jj], acc[i][jj]);
                }
                __syncthreads();
            }
            float* pOut = g_p1[kc];
            int jg = jt * 64 + tx * 4;
            #pragma unroll
            for (int i = 0; i < 4; i++) {
                int b = ty * 4 + i;
                float4 v = {acc[i][0], acc[i][1], acc[i][2], acc[i][3]};
                *reinterpret_cast<float4*>(&pOut[b * 1024 + jg]) = v;
            }
        }
        gridsync();

        // ------------- Phase BC: attention + softmax + ctx (block = b)
        {
            const int b = bx;
            float* hU = smem;            // 512
            float* gs = smem + 512;      // 512
            float* es = smem + 1024;     // 576
            float* red = smem + 1600;    // 32
            {
                int d = tid;
                float s = Ub[d], g = fbb[d];
                #pragma unroll
                for (int kc = 0; kc < 8; kc++) {
                    s += g_p1[kc][b * 1024 + d];
                    g += g_p1[kc][b * 1024 + 512 + d];
                }
                hU[d] = s; gs[d] = fast_sigmoid(g);
            }
            __syncthreads();
            // hoist per-lane hU and v chunks into registers
            float hUr[16], vsr[16];
            #pragma unroll
            for (int k = 0; k < 2; k++)
                #pragma unroll
                for (int j = 0; j < 8; j++) {
                    int d = lane * 8 + k * 256 + j;
                    hUr[k * 8 + j] = hU[d];
                    vsr[k * 8 + j] = vw[d];
                }
            float vb0 = vb[0];
            // scores: 4 rows/warp, MLP 8
            const __half* wsb = g_Ws + (size_t)b * (Pz * 512);
            for (int p0 = wid * 4; p0 < Pz; p0 += 64) {
                const __half* w0 = wsb + (size_t)p0 * 512 + lane * 8;
                uint4 u[8];
                #pragma unroll
                for (int rr = 0; rr < 4; rr++) {
                    u[rr * 2 + 0] = *reinterpret_cast<const uint4*>(w0 + rr * 512);
                    u[rr * 2 + 1] = *reinterpret_cast<const uint4*>(w0 + rr * 512 + 256);
                }
                float a[4] = {};
                #pragma unroll
                for (int rr = 0; rr < 4; rr++) {
                    #pragma unroll
                    for (int k = 0; k < 2; k++) {
                        float f[8]; h8_to_f(u[rr * 2 + k], f);
                        #pragma unroll
                        for (int j = 0; j < 8; j++)
                            a[rr] = fmaf(vsr[k * 8 + j],
                                         tanh_mufu(f[j] + hUr[k * 8 + j]), a[rr]);
                    }
                }
                #pragma unroll
                for (int o = 16; o; o >>= 1) {
                    a[0] += __shfl_down_sync(0xffffffffu, a[0], o);
                    a[1] += __shfl_down_sync(0xffffffffu, a[1], o);
                    a[2] += __shfl_down_sync(0xffffffffu, a[2], o);
                    a[3] += __shfl_down_sync(0xffffffffu, a[3], o);
                }
                if (lane == 0) {
                    es[p0 + 0] = a[0] + vb0; es[p0 + 1] = a[1] + vb0;
                    es[p0 + 2] = a[2] + vb0; es[p0 + 3] = a[3] + vb0;
                }
            }
            __syncthreads();
            // softmax over 576 (warp-shuffle reductions)
            float lmax = -1e30f;
            for (int p = tid; p < Pz; p += NTHR) lmax = fmaxf(lmax, es[p]);
            #pragma unroll
            for (int o = 16; o; o >>= 1)
                lmax = fmaxf(lmax, __shfl_xor_sync(0xffffffffu, lmax, o));
            if (lane == 0) red[wid] = lmax;
            __syncthreads();
            if (tid < 32) {
                float v = (tid < 16) ? red[tid] : -1e30f;
                #pragma unroll
                for (int o = 8; o; o >>= 1)
                    v = fmaxf(v, __shfl_xor_sync(0xffffffffu, v, o));
                if (tid == 0) red[16] = v;
            }
            __syncthreads();
            float mx = red[16];
            float ls = 0.f;
            for (int p = tid; p < Pz; p += NTHR) {
                float v = __expf(es[p] - mx);
                es[p] = v; ls += v;
            }
            #pragma unroll
            for (int o = 16; o; o >>= 1) ls += __shfl_xor_sync(0xffffffffu, ls, o);
            if (lane == 0) red[wid] = ls;
            __syncthreads();
            if (tid < 32) {
                float v = (tid < 16) ? red[tid] : 0.f;
                #pragma unroll
                for (int o = 8; o; o >>= 1) v += __shfl_xor_sync(0xffffffffu, v, o);
                if (tid == 0) red[17] = 1.0f / v;
            }
            __syncthreads();
            float inv = red[17];
            float msk = ((lengths[b] - 1) > t) ? 1.0f : 0.0f;
            for (int p = tid; p < Pz; p += NTHR) {
                float a = es[p] * inv;
                es[p] = a;
                alphas_out[((size_t)b * TM1 + t) * Pz + p] = a * msk;
            }
            __syncthreads();
            // hoist alpha chunks
            float esr[16];
            #pragma unroll
            for (int k = 0; k < 2; k++)
                #pragma unroll
                for (int j = 0; j < 8; j++)
                    esr[k * 8 + j] = es[lane * 8 + k * 256 + j];
            float est[8];
            if (lane < 8) {
                #pragma unroll
                for (int j = 0; j < 8; j++) est[j] = es[512 + lane * 8 + j];
            }
            // ctx: 4 rows/warp
            const __half* fhb = g_featsh + (size_t)b * EP;
            for (int e0 = wid * 4; e0 < 512; e0 += 64) {
                const __half* s0 = fhb + (size_t)e0 * Pz + lane * 8;
                uint4 u[8]; uint4 ut[4];
                #pragma unroll
                for (int rr = 0; rr < 4; rr++) {
                    u[rr * 2 + 0] = *reinterpret_cast<const uint4*>(s0 + rr * Pz);
                    u[rr * 2 + 1] = *reinterpret_cast<const uint4*>(s0 + rr * Pz + 256);
                }
                if (lane < 8) {
                    const __half* sT = fhb + (size_t)e0 * Pz + 512 + lane * 8;
                    #pragma unroll
                    for (int rr = 0; rr < 4; rr++)
                        ut[rr] = *reinterpret_cast<const uint4*>(sT + rr * Pz);
                }
                float a[4] = {};
                #pragma unroll
                for (int rr = 0; rr < 4; rr++) {
                    #pragma unroll
                    for (int k = 0; k < 2; k++) {
                        float f[8]; h8_to_f(u[rr * 2 + k], f);
                        #pragma unroll
                        for (int j = 0; j < 8; j++)
                            a[rr] = fmaf(f[j], esr[k * 8 + j], a[rr]);
                    }
                }
                if (lane < 8) {
                    #pragma unroll
                    for (int rr = 0; rr < 4; rr++) {
                        float f[8]; h8_to_f(ut[rr], f);
                        #pragma unroll
                        for (int j = 0; j < 8; j++)
                            a[rr] = fmaf(f[j], est[j], a[rr]);
                    }
                }
                #pragma unroll
                for (int o = 16; o; o >>= 1) {
                    a[0] += __shfl_down_sync(0xffffffffu, a[0], o);
                    a[1] += __shfl_down_sync(0xffffffffu, a[1], o);
                    a[2] += __shfl_down_sync(0xffffffffu, a[2], o);
                    a[3] += __shfl_down_sync(0xffffffffu, a[3], o);
                }
                if (lane == 0) {
                    #pragma unroll
                    for (int rr = 0; rr < 4; rr++)
                        g_xin[b * 512 + e0 + rr] = gs[e0 + rr] * a[rr];
                }
            }
        }
        gridsync();

        // ------------- Phase D: LSTM gemm K=1024 balanced, FFMA2, double-buffer
        {
            int kc = bx & 1, jt = bx >> 1;
            int j0 = jt * 32;
            const float* A; const float* W; int ldw, wk;
            if (kc == 0) { A = g_xin; W = wih; ldw = 1024; wk = 512; }
            else         { A = h;     W = whh; ldw = 512;  wk = 0;   }
            float* AsT = smem;                                       // [32][130]
            unsigned long long* Bs2 =
                reinterpret_cast<unsigned long long*>(smem + 4160);  // [32][32]
            int tx = tid & 7, ty = tid >> 3;       // ty 0..63 (batch pair)
            int ab = tid >> 2, aq = (tid & 3) * 8; // A loader
            int wj = tid & 31, wq = (tid >> 5) * 4;// W loader (tid<256)
            unsigned long long acc[4] = {0ull, 0ull, 0ull, 0ull};
            float4 a0v = *reinterpret_cast<const float4*>(&A[ab * 512 + aq]);
            float4 a1v = *reinterpret_cast<const float4*>(&A[ab * 512 + aq + 4]);
            float4 wv;
            if (tid < 256)
                wv = *reinterpret_cast<const float4*>(&W[(j0 + wj) * ldw + wk + wq]);
            for (int kk = 0; kk < 512; kk += 32) {
                __syncthreads();
                #pragma unroll
                for (int i = 0; i < 4; i++) {
                    AsT[(aq + i) * 130 + ab]     = (&a0v.x)[i];
                    AsT[(aq + 4 + i) * 130 + ab] = (&a1v.x)[i];
                }
                if (tid < 256) {
                    #pragma unroll
                    for (int i = 0; i < 4; i++)
                        Bs2[(wq + i) * 32 + wj] = pack2dup((&wv.x)[i]);
                }
                __syncthreads();
                if (kk + 32 < 512) {
                    a0v = *reinterpret_cast<const float4*>(&A[ab * 512 + kk + 32 + aq]);
                    a1v = *reinterpret_cast<const float4*>(&A[ab * 512 + kk + 32 + aq + 4]);
                    if (tid < 256)
                        wv = *reinterpret_cast<const float4*>(&W[(j0 + wj) * ldw + wk + kk + 32 + wq]);
                }
                #pragma unroll
                for (int r = 0; r < 32; r++) {
                    unsigned long long apair =
                        *reinterpret_cast<const unsigned long long*>(&AsT[r * 130 + ty * 2]);
                    #pragma unroll
                    for (int jj = 0; jj < 4; jj++)
                        ffma2(acc[jj], apair, Bs2[r * 32 + tx * 4 + jj]);
                }
            }
            float* pOut = g_part[kc];
            int jg = j0 + tx * 4;
            float o0[4], o1[4];
            #pragma unroll
            for (int jj = 0; jj < 4; jj++) unpack2(acc[jj], o0[jj], o1[jj]);
            float4 v0 = {o0[0], o0[1], o0[2], o0[3]};
            float4 v1 = {o1[0], o1[1], o1[2], o1[3]};
            *reinterpret_cast<float4*>(&pOut[(ty * 2) * 2048 + jg]) = v0;
            *reinterpret_cast<float4*>(&pOut[(ty * 2 + 1) * 2048 + jg]) = v1;
        }
        gridsync();

        // ------------- Phase E: reduce + embW + LSTM cell + pred gemm
        {
            const int b = bx;
            float* h2s = smem;
            const float* cprev = g_c[cur];
            float* cnext = g_c[cur ^ 1];
            float* hnext = g_h[cur ^ 1];
            int cap = captions[b * Tz + t];
            const float* ew = g_embW + (size_t)cap * 2048;
            {
                int d = tid;
                float gi = bih[d]        + bhh[d]        + ew[d];
                float gf = bih[512 + d]  + bhh[512 + d]  + ew[512 + d];
                float gg = bih[1024 + d] + bhh[1024 + d] + ew[1024 + d];
                float go = bih[1536 + d] + bhh[1536 + d] + ew[1536 + d];
                #pragma unroll
                for (int s = 0; s < 2; s++) {
                    const float* gp = g_part[s] + b * 2048;
                    gi += gp[d]; gf += gp[512 + d]; gg += gp[1024 + d]; go += gp[1536 + d];
                }
                float c2 = fast_sigmoid(gf) * cprev[b * 512 + d]
                         + fast_sigmoid(gi) * fast_tanh(gg);
                float h2 = fast_sigmoid(go) * fast_tanh(c2);
                cnext[b * 512 + d] = c2;
                hnext[b * 512 + d] = h2;
                h2s[d] = h2;
            }
            __syncthreads();
            float msk = ((lengths[b] - 1) > t) ? 1.0f : 0.0f;
            if (tid < Vz) {
                const float* row = g_fcwT + tid * 512;
                unsigned long long acc2[4] = {0ull, 0ull, 0ull, 0ull};
                #pragma unroll 8
                for (int d = 0; d < 512; d += 8) {
                    ulonglong2 w0 = *reinterpret_cast<const ulonglong2*>(row + d);
                    ulonglong2 w1 = *reinterpret_cast<const ulonglong2*>(row + d + 4);
                    ulonglong2 h0 = *reinterpret_cast<const ulonglong2*>(h2s + d);
                    ulonglong2 h1 = *reinterpret_cast<const ulonglong2*>(h2s + d + 4);
                    ffma2(acc2[0], w0.x, h0.x);
                    ffma2(acc2[1], w0.y, h0.y);
                    ffma2(acc2[2], w1.x, h1.x);
                    ffma2(acc2[3], w1.y, h1.y);
                }
                float s = fcb[tid];
                #pragma unroll
                for (int jj = 0; jj < 4; jj++) {
                    float lo, hi; unpack2(acc2[jj], lo, hi);
                    s += lo + hi;
                }
                preds_out[((size_t)b * TM1 + t) * Vz + tid] = s * msk;
            }
            __syncthreads();
        }
        gridsync();
    }
}

// ---------------- launch ------------------------------------------------------
extern "C" void kernel_launch(void* const* d_in, const int* in_sizes, int n_in,
                              void* d_out, int out_size) {
    const float* feats    = (const float*)d_in[0];
    const int*   captions = (const int*)d_in[1];
    const int*   lengths  = (const int*)d_in[2];
    const float* U_w  = (const float*)d_in[3];
    const float* U_b  = (const float*)d_in[4];
    const float* W_w  = (const float*)d_in[5];
    const float* W_b  = (const float*)d_in[6];
    const float* v_w  = (const float*)d_in[7];
    const float* v_b  = (const float*)d_in[8];
    const float* ihw  = (const float*)d_in[9];
    const float* ihb  = (const float*)d_in[10];
    const float* icw  = (const float*)d_in[11];
    const float* icb  = (const float*)d_in[12];
    const float* fbw  = (const float*)d_in[13];
    const float* fbb  = (const float*)d_in[14];
    const float* fcw  = (const float*)d_in[15];
    const float* fcb  = (const float*)d_in[16];
    const float* emb  = (const float*)d_in[17];
    const float* wih  = (const float*)d_in[18];
    const float* whh  = (const float*)d_in[19];
    const float* bih  = (const float*)d_in[20];
    const float* bhh  = (const float*)d_in[21];

    float* out    = (float*)d_out;
    float* preds  = out;
    float* alphas = out + (size_t)Bz * TM1 * Vz;
    float* dec    = alphas + (size_t)Bz * TM1 * Pz;

    prep_misc_kernel<<<8743, 256>>>(feats, fcw, lengths, dec);
    prep2_kernel<<<18448, 256>>>(feats, ihw, icw, ihb, icb);
    embw_kernel<<<dim3(2, 69), 512>>>(emb, ihw ? wih : wih);  // wih
    ws_gemm_kernel<<<dim3(9, 8, Bz), 256>>>(feats, W_w, W_b);
    decode_kernel<<<GRID, NTHR>>>(U_w, U_b, v_w, v_b, fbw, fbb,
                                  captions, lengths,
                                  wih, whh, bih, bhh, fcb,
                                  preds, alphas);
    (void)in_sizes; (void)n_in; (void)out_size;
}

// round 6
// speedup vs baseline: 1.2495x; 1.2495x over previous
#include <cuda_runtime.h>
#include <cuda_fp16.h>
#include <cstdint>
#include <cstddef>

#define Bz 128
#define Ez 512
#define Dz 512
#define Vz 275
#define Pz 576
#define Tz 300
#define TM1 299
#define EP (Ez*Pz)
#define GRID 128
#define NTHR 512

// ---------------- scratch (device globals; no allocs allowed) ----------------
__device__ __half g_Ws[(size_t)Bz*Pz*Dz];     // 75.5 MB fp16: flat@W_w + W_b
__device__ __half g_featsh[(size_t)Bz*EP];    // 75.5 MB fp16 copy of feats
__device__ float g_fcwT[Vz*Dz];               // transposed fc weights [V][D]
__device__ float g_embW[Vz*2048];             // emb @ wih[:, :512]^T  [V][4D]
__device__ float g_mean[Bz*Ez];
__device__ float g_h[2][Bz*Dz];
__device__ float g_c[2][Bz*Dz];
__device__ float g_p1[8][Bz*1024];            // per-step split-K partials (hU|gate)
__device__ float g_xin[Bz*Dz];                // gate*ctx only (emb via embW)
__device__ float g_part[2][Bz*2048];          // split-K partials for LSTM gemm

// ---------------- software grid barrier --------------------------------------
__device__ unsigned g_bar_count;
__device__ volatile unsigned g_bar_gen;

__device__ __forceinline__ void gridsync() {
    __syncthreads();
    if (threadIdx.x == 0) {
        __threadfence();
        unsigned gen = g_bar_gen;
        if (atomicAdd(&g_bar_count, 1u) == GRID - 1) {
            g_bar_count = 0;
            __threadfence();
            g_bar_gen = gen + 1;
        } else {
            while (g_bar_gen == gen) {}
        }
        __threadfence();
    }
    __syncthreads();
}

// ---------------- activation helpers -----------------------------------------
__device__ __forceinline__ float tanh_mufu(float x) {
    float y; asm("tanh.approx.f32 %0, %1;" : "=f"(y) : "f"(x));
    return y;
}
__device__ __forceinline__ float fast_tanh(float x) {
    float t = fminf(fmaxf(x * 2.885390081777927f, -252.0f), 252.0f);
    float z; asm("ex2.approx.f32 %0, %1;" : "=f"(z) : "f"(t));
    float den = z + 1.0f;
    float r; asm("rcp.approx.f32 %0, %1;" : "=f"(r) : "f"(den));
    return (z - 1.0f) * r;
}
__device__ __forceinline__ float fast_sigmoid(float x) {
    float t = fminf(fmaxf(x * -1.4426950408889634f, -252.0f), 252.0f);
    float z; asm("ex2.approx.f32 %0, %1;" : "=f"(z) : "f"(t));
    float den = z + 1.0f;
    float r; asm("rcp.approx.f32 %0, %1;" : "=f"(r) : "f"(den));
    return r;
}
__device__ __forceinline__ void h8_to_f(const uint4& u, float* f) {
    float2 a = __half22float2(*reinterpret_cast<const __half2*>(&u.x));
    float2 b = __half22float2(*reinterpret_cast<const __half2*>(&u.y));
    float2 c = __half22float2(*reinterpret_cast<const __half2*>(&u.z));
    float2 d = __half22float2(*reinterpret_cast<const __half2*>(&u.w));
    f[0]=a.x; f[1]=a.y; f[2]=b.x; f[3]=b.y; f[4]=c.x; f[5]=c.y; f[6]=d.x; f[7]=d.y;
}

// ======= launch 1: mean + fcw transpose + embW + dec_len =====================
__global__ void prep_misc_kernel(const float* __restrict__ feats,
                                 const float* __restrict__ fcw,
                                 const float* __restrict__ emb,
                                 const float* __restrict__ wih,
                                 const int* __restrict__ lengths,
                                 float* __restrict__ dec) {
    __shared__ float er[512];
    int bx = blockIdx.x, tid = threadIdx.x;
    if (bx < 8192) {                                  // mean over P
        int warp = tid >> 5, lane = tid & 31;
        int idx = bx * 8 + warp;
        int b = idx >> 9, e = idx & 511;
        const float* src = feats + (size_t)b * EP + (size_t)e * Pz;
        float acc = 0.f;
        #pragma unroll
        for (int k = 0; k < 18; k++) acc += src[lane + k * 32];
        #pragma unroll
        for (int o = 16; o; o >>= 1) acc += __shfl_down_sync(0xffffffffu, acc, o);
        if (lane == 0) g_mean[idx] = acc * (1.0f / 576.0f);
    } else if (bx < 8742) {                           // fcw transpose
        int idx = (bx - 8192) * 256 + tid;
        int v = idx >> 9, d = idx & 511;
        g_fcwT[v * 512 + d] = fcw[d * Vz + v];
    } else if (bx < 9017) {                           // embW: one token per block
        int v = bx - 8742;                            // 0..274
        for (int i = tid; i < 512; i += 256) er[i] = emb[v * 512 + i];
        __syncthreads();
        for (int j = tid; j < 2048; j += 256) {
            const float* wr = wih + (size_t)j * 1024;
            float a0 = 0.f, a1 = 0.f, a2 = 0.f, a3 = 0.f;
            #pragma unroll 8
            for (int k = 0; k < 512; k += 4) {
                float4 w = *reinterpret_cast<const float4*>(wr + k);
                float4 e4 = *reinterpret_cast<const float4*>(&er[k]);
                a0 = fmaf(w.x, e4.x, a0);
                a1 = fmaf(w.y, e4.y, a1);
                a2 = fmaf(w.z, e4.z, a2);
                a3 = fmaf(w.w, e4.w, a3);
            }
            g_embW[v * 2048 + j] = (a0 + a1) + (a2 + a3);
        }
    } else {                                          // dec_len
        if (tid < Bz) dec[tid] = (float)(lengths[tid] - 1);
    }
}

// ======= launch 2: f2h + init h0/c0 gemm =====================================
__global__ void prep2_kernel(const float* __restrict__ feats,
                             const float* __restrict__ W1,
                             const float* __restrict__ W2,
                             const float* __restrict__ b1,
                             const float* __restrict__ b2) {
    int bx = blockIdx.x, tid = threadIdx.x;
    if (bx < 18432) {
        size_t i = ((size_t)bx * 256 + tid) * 8;
        float4 v0 = *reinterpret_cast<const float4*>(feats + i);
        float4 v1 = *reinterpret_cast<const float4*>(feats + i + 4);
        __half2 h0 = __floats2half2_rn(v0.x, v0.y);
        __half2 h1 = __floats2half2_rn(v0.z, v0.w);
        __half2 h2 = __floats2half2_rn(v1.x, v1.y);
        __half2 h3 = __floats2half2_rn(v1.z, v1.w);
        uint4 o;
        o.x = *reinterpret_cast<unsigned*>(&h0);
        o.y = *reinterpret_cast<unsigned*>(&h1);
        o.z = *reinterpret_cast<unsigned*>(&h2);
        o.w = *reinterpret_cast<unsigned*>(&h3);
        *reinterpret_cast<uint4*>(g_featsh + i) = o;
        return;
    }
    int jt = bx - 18432;
    const float* W = (jt < 8) ? W1 : W2;
    const float* bias = (jt < 8) ? b1 : b2;
    int wj0 = ((jt < 8) ? jt : jt - 8) * 64;
    __shared__ float As[8][128];
    __shared__ float Bs[8][64];
    int tx = tid & 15, ty = tid >> 4;
    float acc[8][4] = {};
    for (int kk = 0; kk < 512; kk += 8) {
        {
            int b = tid >> 1, r4 = (tid & 1) * 4;
            float4 v = *reinterpret_cast<const float4*>(&g_mean[b * 512 + kk + r4]);
            As[r4 + 0][b] = v.x; As[r4 + 1][b] = v.y; As[r4 + 2][b] = v.z; As[r4 + 3][b] = v.w;
        }
        if (tid < 128) {
            int j4 = (tid & 15) * 4, r = tid >> 4;
            float4 v = *reinterpret_cast<const float4*>(&W[(kk + r) * 512 + wj0 + j4]);
            Bs[r][j4 + 0] = v.x; Bs[r][j4 + 1] = v.y; Bs[r][j4 + 2] = v.z; Bs[r][j4 + 3] = v.w;
        }
        __syncthreads();
        #pragma unroll
        for (int r = 0; r < 8; r++) {
            float4 w4 = *reinterpret_cast<const float4*>(&Bs[r][tx * 4]);
            float4 a0 = *reinterpret_cast<const float4*>(&As[r][ty * 8]);
            float4 a1 = *reinterpret_cast<const float4*>(&As[r][ty * 8 + 4]);
            float a[8] = {a0.x, a0.y, a0.z, a0.w, a1.x, a1.y, a1.z, a1.w};
            float w[4] = {w4.x, w4.y, w4.z, w4.w};
            #pragma unroll
            for (int i = 0; i < 8; i++)
                #pragma unroll
                for (int jj = 0; jj < 4; jj++)
                    acc[i][jj] = fmaf(a[i], w[jj], acc[i][jj]);
        }
        __syncthreads();
    }
    float* dst = (jt < 8) ? g_h[0] : g_c[0];
    int j = wj0 + tx * 4;
    float4 bb = *reinterpret_cast<const float4*>(&bias[j]);
    #pragma unroll
    for (int i = 0; i < 8; i++) {
        int b = ty * 8 + i;
        float4 v = {acc[i][0] + bb.x, acc[i][1] + bb.y, acc[i][2] + bb.z, acc[i][3] + bb.w};
        *reinterpret_cast<float4*>(&dst[b * 512 + j]) = v;
    }
}

// ======= launch 3: Ws precompute (fp16) ======================================
__global__ void ws_gemm_kernel(const float* __restrict__ feats,
                               const float* __restrict__ Ww,
                               const float* __restrict__ Wb) {
    int b = blockIdx.z;
    int p0 = blockIdx.x * 64;
    int d0 = blockIdx.y * 64;
    __shared__ float As[8][64];
    __shared__ float Bs[8][64];
    int tid = threadIdx.x, tx = tid & 15, ty = tid >> 4;
    float acc[4][4] = {};
    const float* fb = feats + (size_t)b * EP;
    for (int kk = 0; kk < 512; kk += 8) {
        if (tid < 128) {
            int p4 = (tid & 15) * 4, r = tid >> 4;
            float4 v = *reinterpret_cast<const float4*>(&fb[(size_t)(kk + r) * Pz + p0 + p4]);
            As[r][p4 + 0] = v.x; As[r][p4 + 1] = v.y; As[r][p4 + 2] = v.z; As[r][p4 + 3] = v.w;
        } else {
            int t2 = tid - 128;
            int d4 = (t2 & 15) * 4, r = t2 >> 4;
            float4 v = *reinterpret_cast<const float4*>(&Ww[(kk + r) * 512 + d0 + d4]);
            Bs[r][d4 + 0] = v.x; Bs[r][d4 + 1] = v.y; Bs[r][d4 + 2] = v.z; Bs[r][d4 + 3] = v.w;
        }
        __syncthreads();
        #pragma unroll
        for (int r = 0; r < 8; r++) {
            float4 a4 = *reinterpret_cast<const float4*>(&As[r][ty * 4]);
            float4 w4 = *reinterpret_cast<const float4*>(&Bs[r][tx * 4]);
            float a[4] = {a4.x, a4.y, a4.z, a4.w};
            float w[4] = {w4.x, w4.y, w4.z, w4.w};
            #pragma unroll
            for (int i = 0; i < 4; i++)
                #pragma unroll
                for (int jj = 0; jj < 4; jj++)
                    acc[i][jj] = fmaf(a[i], w[jj], acc[i][jj]);
        }
        __syncthreads();
    }
    float4 wb4 = *reinterpret_cast<const float4*>(&Wb[d0 + tx * 4]);
    #pragma unroll
    for (int i = 0; i < 4; i++) {
        size_t row = (size_t)(b * Pz + p0 + ty * 4 + i);
        __half2 h01 = __floats2half2_rn(acc[i][0] + wb4.x, acc[i][1] + wb4.y);
        __half2 h23 = __floats2half2_rn(acc[i][2] + wb4.z, acc[i][3] + wb4.w);
        uint2 u;
        u.x = *reinterpret_cast<unsigned*>(&h01);
        u.y = *reinterpret_cast<unsigned*>(&h23);
        *reinterpret_cast<uint2*>(&g_Ws[row * 512 + d0 + tx * 4]) = u;
    }
}

// ============================================================================
//  launch 4 (PROFILED): persistent decode, 299 steps, 4 phases/step
// ============================================================================
__global__ void __launch_bounds__(NTHR, 1) decode_kernel(
    const float* __restrict__ Uw,  const float* __restrict__ Ub,
    const float* __restrict__ vw,  const float* __restrict__ vb,
    const float* __restrict__ fbw, const float* __restrict__ fbb,
    const int*   __restrict__ captions,
    const int*   __restrict__ lengths,
    const float* __restrict__ wih, const float* __restrict__ whh,
    const float* __restrict__ bih, const float* __restrict__ bhh,
    const float* __restrict__ fcb,
    float* __restrict__ preds_out, float* __restrict__ alphas_out)
{
    __shared__ float smem[5664];   // D: As 128*36=4608 + Bs 32*32=1024 = 5632
    const int bx = blockIdx.x, tid = threadIdx.x;
    const int wid = tid >> 5, lane = tid & 31;

    for (int t = 0; t < TM1; t++) {
        const int cur = t & 1;
        const float* h = g_h[cur];

        // ------------- Phase A: (hU | gate-raw) partials = h @ (U_w | f_beta_w)
        {
            int jt = bx & 15, kc = bx >> 4;          // 16 j-tiles x 8 k-chunks
            const float* W = (jt < 8) ? Uw : fbw;
            int wj0 = ((jt < 8) ? jt : jt - 8) * 64;
            int k0 = kc * 64;
            float* As = smem;            // [8][128]
            float* Bs = smem + 1024;     // [8][64]
            int tx = tid & 15, ty = tid >> 4;        // ty 0..31
            float acc[4][4] = {};
            for (int kk = 0; kk < 64; kk += 8) {
                if (tid < 256) {
                    int b = tid >> 1, r4 = (tid & 1) * 4;
                    float4 v = *reinterpret_cast<const float4*>(&h[b * 512 + k0 + kk + r4]);
                    As[(r4 + 0) * 128 + b] = v.x; As[(r4 + 1) * 128 + b] = v.y;
                    As[(r4 + 2) * 128 + b] = v.z; As[(r4 + 3) * 128 + b] = v.w;
                } else if (tid < 384) {
                    int t2 = tid - 256;
                    int j4 = (t2 & 15) * 4, r = t2 >> 4;
                    float4 v = *reinterpret_cast<const float4*>(&W[(k0 + kk + r) * 512 + wj0 + j4]);
                    Bs[r * 64 + j4 + 0] = v.x; Bs[r * 64 + j4 + 1] = v.y;
                    Bs[r * 64 + j4 + 2] = v.z; Bs[r * 64 + j4 + 3] = v.w;
                }
                __syncthreads();
                #pragma unroll
                for (int r = 0; r < 8; r++) {
                    float4 w4 = *reinterpret_cast<const float4*>(&Bs[r * 64 + tx * 4]);
                    float4 a4 = *reinterpret_cast<const float4*>(&As[r * 128 + ty * 4]);
                    float a[4] = {a4.x, a4.y, a4.z, a4.w};
                    float w[4] = {w4.x, w4.y, w4.z, w4.w};
                    #pragma unroll
                    for (int i = 0; i < 4; i++)
                        #pragma unroll
                        for (int jj = 0; jj < 4; jj++)
                            acc[i][jj] = fmaf(a[i], w[jj], acc[i][jj]);
                }
                __syncthreads();
            }
            float* pOut = g_p1[kc];
            int jg = jt * 64 + tx * 4;
            #pragma unroll
            for (int i = 0; i < 4; i++) {
                int b = ty * 4 + i;
                float4 v = {acc[i][0], acc[i][1], acc[i][2], acc[i][3]};
                *reinterpret_cast<float4*>(&pOut[b * 1024 + jg]) = v;
            }
        }
        gridsync();

        // ------------- Phase BC: attention + softmax + ctx (block = b)  [R4]
        {
            const int b = bx;
            float* hU = smem;            // 512
            float* vs = smem + 512;      // 512
            float* gs = smem + 1024;     // 512
            float* es = smem + 1536;     // 576
            float* red = smem + 2112;    // 512
            {
                int d = tid;
                float s = Ub[d], g = fbb[d];
                #pragma unroll
                for (int kc = 0; kc < 8; kc++) {
                    s += g_p1[kc][b * 1024 + d];
                    g += g_p1[kc][b * 1024 + 512 + d];
                }
                hU[d] = s; vs[d] = vw[d]; gs[d] = fast_sigmoid(g);
            }
            __syncthreads();
            // attention scores: 2 rows per warp, fp16 Ws stream, MUFU tanh
            float vb0 = vb[0];
            const __half* wsb = g_Ws + (size_t)b * (Pz * 512);
            for (int p = wid * 2; p < Pz; p += 32) {
                const __half* w0 = wsb + (size_t)p * 512;
                const __half* w1 = w0 + 512;
                float a0 = 0.f, a1 = 0.f;
                #pragma unroll
                for (int k = 0; k < 2; k++) {
                    int d = lane * 8 + k * 256;
                    uint4 u0 = *reinterpret_cast<const uint4*>(w0 + d);
                    uint4 u1 = *reinterpret_cast<const uint4*>(w1 + d);
                    float f0[8], f1[8];
                    h8_to_f(u0, f0); h8_to_f(u1, f1);
                    #pragma unroll
                    for (int j = 0; j < 8; j++) {
                        float hv = hU[d + j], vv = vs[d + j];
                        a0 = fmaf(vv, tanh_mufu(f0[j] + hv), a0);
                        a1 = fmaf(vv, tanh_mufu(f1[j] + hv), a1);
                    }
                }
                #pragma unroll
                for (int o = 16; o; o >>= 1) {
                    a0 += __shfl_down_sync(0xffffffffu, a0, o);
                    a1 += __shfl_down_sync(0xffffffffu, a1, o);
                }
                if (lane == 0) { es[p] = a0 + vb0; es[p + 1] = a1 + vb0; }
            }
            __syncthreads();
            // softmax over 576
            float lmax = -1e30f;
            for (int p = tid; p < Pz; p += NTHR) lmax = fmaxf(lmax, es[p]);
            red[tid] = lmax; __syncthreads();
            for (int o = 256; o; o >>= 1) {
                if (tid < o) red[tid] = fmaxf(red[tid], red[tid + o]);
                __syncthreads();
            }
            float mx = red[0]; __syncthreads();
            float ls = 0.f;
            for (int p = tid; p < Pz; p += NTHR) {
                float v = __expf(es[p] - mx);
                es[p] = v; ls += v;
            }
            red[tid] = ls; __syncthreads();
            for (int o = 256; o; o >>= 1) {
                if (tid < o) red[tid] += red[tid + o];
                __syncthreads();
            }
            float inv = 1.0f / red[0];
            float msk = ((lengths[b] - 1) > t) ? 1.0f : 0.0f;
            for (int p = tid; p < Pz; p += NTHR) {
                float a = es[p] * inv;
                es[p] = a;
                alphas_out[((size_t)b * TM1 + t) * Pz + p] = a * msk;
            }
            __syncthreads();
            // ctx: xin[e] = gate[e] * sum_p alpha[p] * feats[b,e,p]
            const __half* fhb = g_featsh + (size_t)b * EP;
            for (int e = wid * 2; e < 512; e += 32) {
                const __half* s0 = fhb + (size_t)e * Pz;
                const __half* s1 = s0 + Pz;
                float a0 = 0.f, a1 = 0.f;
                #pragma unroll
                for (int k = 0; k < 2; k++) {
                    int d = lane * 8 + k * 256;
                    uint4 u0 = *reinterpret_cast<const uint4*>(s0 + d);
                    uint4 u1 = *reinterpret_cast<const uint4*>(s1 + d);
                    float f0[8], f1[8];
                    h8_to_f(u0, f0); h8_to_f(u1, f1);
                    #pragma unroll
                    for (int j = 0; j < 8; j++) {
                        float av = es[d + j];
                        a0 = fmaf(f0[j], av, a0);
                        a1 = fmaf(f1[j], av, a1);
                    }
                }
                if (lane < 8) {          // tail p = 512..575
                    int d = 512 + lane * 8;
                    uint4 u0 = *reinterpret_cast<const uint4*>(s0 + d);
                    uint4 u1 = *reinterpret_cast<const uint4*>(s1 + d);
                    float f0[8], f1[8];
                    h8_to_f(u0, f0); h8_to_f(u1, f1);
                    #pragma unroll
                    for (int j = 0; j < 8; j++) {
                        float av = es[d + j];
                        a0 = fmaf(f0[j], av, a0);
                        a1 = fmaf(f1[j], av, a1);
                    }
                }
                #pragma unroll
                for (int o = 16; o; o >>= 1) {
                    a0 += __shfl_down_sync(0xffffffffu, a0, o);
                    a1 += __shfl_down_sync(0xffffffffu, a1, o);
                }
                if (lane == 0) {
                    g_xin[b * 512 + e]     = gs[e] * a0;
                    g_xin[b * 512 + e + 1] = gs[e + 1] * a1;
                }
            }
        }
        gridsync();

        // ------------- Phase D: LSTM gemm K=1024 balanced (512/512), k-tile 32
        {
            int kc = bx & 1, jt = bx >> 1;
            int j0 = jt * 32;
            const float* A = (kc == 0) ? g_xin + 0 : h;   // both lda = 512
            const float* W; int ldw, wk;
            if (kc == 0) { W = wih; ldw = 1024; wk = 512; }
            else         { W = whh; ldw = 512;  wk = 0;   }
            float* As = smem;            // [128][36] padded
            float* Bs = smem + 4608;     // [32][32]
            int tx = tid & 7, ty = tid >> 3;          // ty 0..63
            int b0 = ty * 2, b1 = ty * 2 + 1;
            float acc[2][4] = {};
            for (int kk = 0; kk < 512; kk += 32) {
                {   // load A tile: 128 b x 32 k
                    int b = tid >> 2, q = (tid & 3) * 8;
                    float4 v0 = *reinterpret_cast<const float4*>(&A[b * 512 + kk + q]);
                    float4 v1 = *reinterpret_cast<const float4*>(&A[b * 512 + kk + q + 4]);
                    *reinterpret_cast<float4*>(&As[b * 36 + q]) = v0;
                    *reinterpret_cast<float4*>(&As[b * 36 + q + 4]) = v1;
                }
                if (tid < 256) {   // load W tile: 32 j x 32 k -> Bs[k][j]
                    int j = tid & 31, kq = (tid >> 5) * 4;
                    float4 v = *reinterpret_cast<const float4*>(&W[(j0 + j) * ldw + wk + kk + kq]);
                    Bs[(kq + 0) * 32 + j] = v.x;
                    Bs[(kq + 1) * 32 + j] = v.y;
                    Bs[(kq + 2) * 32 + j] = v.z;
                    Bs[(kq + 3) * 32 + j] = v.w;
                }
                __syncthreads();
                #pragma unroll
                for (int r = 0; r < 32; r++) {
                    float4 w4 = *reinterpret_cast<const float4*>(&Bs[r * 32 + tx * 4]);
                    float a0 = As[b0 * 36 + r];
                    float a1 = As[b1 * 36 + r];
                    #pragma unroll
                    for (int jj = 0; jj < 4; jj++) {
                        float w = (&w4.x)[jj];
                        acc[0][jj] = fmaf(a0, w, acc[0][jj]);
                        acc[1][jj] = fmaf(a1, w, acc[1][jj]);
                    }
                }
                __syncthreads();
            }
            float* pOut = g_part[kc];
            int jg = j0 + tx * 4;
            {
                float4 v0 = {acc[0][0], acc[0][1], acc[0][2], acc[0][3]};
                float4 v1 = {acc[1][0], acc[1][1], acc[1][2], acc[1][3]};
                *reinterpret_cast<float4*>(&pOut[b0 * 2048 + jg]) = v0;
                *reinterpret_cast<float4*>(&pOut[b1 * 2048 + jg]) = v1;
            }
        }
        gridsync();

        // ------------- Phase E: reduce + embW + LSTM cell + pred gemm
        {
            const int b = bx;
            float* h2s = smem;           // 512
            const float* cprev = g_c[cur];
            float* cnext = g_c[cur ^ 1];
            float* hnext = g_h[cur ^ 1];
            int cap = captions[b * Tz + t];
            const float* ew = g_embW + (size_t)cap * 2048;
            {
                int d = tid;
                float gi = bih[d]        + bhh[d]        + ew[d];
                float gf = bih[512 + d]  + bhh[512 + d]  + ew[512 + d];
                float gg = bih[1024 + d] + bhh[1024 + d] + ew[1024 + d];
                float go = bih[1536 + d] + bhh[1536 + d] + ew[1536 + d];
                #pragma unroll
                for (int s = 0; s < 2; s++) {
                    const float* gp = g_part[s] + b * 2048;
                    gi += gp[d]; gf += gp[512 + d]; gg += gp[1024 + d]; go += gp[1536 + d];
                }
                float c2 = fast_sigmoid(gf) * cprev[b * 512 + d]
                         + fast_sigmoid(gi) * fast_tanh(gg);
                float h2 = fast_sigmoid(go) * fast_tanh(c2);
                cnext[b * 512 + d] = c2;
                hnext[b * 512 + d] = h2;
                h2s[d] = h2;
            }
            __syncthreads();
            float msk = ((lengths[b] - 1) > t) ? 1.0f : 0.0f;
            if (tid < Vz) {
                int v = tid;
                const float* row = g_fcwT + v * 512;
                float a0 = 0.f, a1 = 0.f, a2 = 0.f, a3 = 0.f;
                #pragma unroll 8
                for (int d = 0; d < 512; d += 4) {
                    float4 w = *reinterpret_cast<const float4*>(row + d);
                    float4 hh = *reinterpret_cast<const float4*>(h2s + d);
                    a0 = fmaf(hh.x, w.x, a0);
                    a1 = fmaf(hh.y, w.y, a1);
                    a2 = fmaf(hh.z, w.z, a2);
                    a3 = fmaf(hh.w, w.w, a3);
                }
                float acc = fcb[v] + ((a0 + a1) + (a2 + a3));
                preds_out[((size_t)b * TM1 + t) * Vz + v] = acc * msk;
            }
            __syncthreads();
        }
        gridsync();
    }
}

// ---------------- launch ------------------------------------------------------
extern "C" void kernel_launch(void* const* d_in, const int* in_sizes, int n_in,
                              void* d_out, int out_size) {
    const float* feats    = (const float*)d_in[0];
    const int*   captions = (const int*)d_in[1];
    const int*   lengths  = (const int*)d_in[2];
    const float* U_w  = (const float*)d_in[3];
    const float* U_b  = (const float*)d_in[4];
    const float* W_w  = (const float*)d_in[5];
    const float* W_b  = (const float*)d_in[6];
    const float* v_w  = (const float*)d_in[7];
    const float* v_b  = (const float*)d_in[8];
    const float* ihw  = (const float*)d_in[9];
    const float* ihb  = (const float*)d_in[10];
    const float* icw  = (const float*)d_in[11];
    const float* icb  = (const float*)d_in[12];
    const float* fbw  = (const float*)d_in[13];
    const float* fbb  = (const float*)d_in[14];
    const float* fcw  = (const float*)d_in[15];
    const float* fcb  = (const float*)d_in[16];
    const float* emb  = (const float*)d_in[17];
    const float* wih  = (const float*)d_in[18];
    const float* whh  = (const float*)d_in[19];
    const float* bih  = (const float*)d_in[20];
    const float* bhh  = (const float*)d_in[21];

    float* out    = (float*)d_out;
    float* preds  = out;
    float* alphas = out + (size_t)Bz * TM1 * Vz;
    float* dec    = alphas + (size_t)Bz * TM1 * Pz;

    // launch 1: mean + fcwT + embW + dec
    prep_misc_kernel<<<9018, 256>>>(feats, fcw, emb, wih, lengths, dec);
    // launch 2: feats->fp16 + init h0/c0
    prep2_kernel<<<18448, 256>>>(feats, ihw, icw, ihb, icb);
    // launch 3: Ws precompute (fp16 out)
    ws_gemm_kernel<<<dim3(9, 8, Bz), 256>>>(feats, W_w, W_b);
    // launch 4 (profiled): persistent decode
    decode_kernel<<<GRID, NTHR>>>(U_w, U_b, v_w, v_b, fbw, fbb,
                                  captions, lengths,
                                  wih, whh, bih, bhh, fcb,
                                  preds, alphas);
    (void)in_sizes; (void)n_in; (void)out_size;
}